// round 3
// baseline (speedup 1.0000x reference)
#include <cuda_runtime.h>
#include <math.h>

#define B_   32
#define D_   128
#define LC_  2048
#define LQ_  512

typedef unsigned long long ull;

// ---------------- scratch (device globals: no alloc allowed) ----------------
__device__ float g_E[(size_t)B_ * LC_ * LQ_];   // E = qmask * exp(S)   (134 MB)
__device__ float g_s0[B_ * LC_];
__device__ float g_s1[B_ * LQ_];
__device__ float g_rZ1[B_ * LC_];
__device__ float g_rZ2[B_ * LQ_];
__device__ float g_T[B_ * LQ_ * D_];            // T = S2^T @ Ct  (8 MB)

// ---------------- packed f32x2 helpers ----------------
__device__ __forceinline__ ull pk2(float x) {
    ull r; asm("mov.b64 %0, {%1, %1};" : "=l"(r) : "f"(x)); return r;
}
__device__ __forceinline__ void fma2(ull &d, ull a, ull b) {
    asm("fma.rn.f32x2 %0, %1, %2, %0;" : "+l"(d) : "l"(a), "l"(b));
}
__device__ __forceinline__ float2 up2(ull v) {
    float2 r; asm("mov.b64 {%0, %1}, %2;" : "=f"(r.x), "=f"(r.y) : "l"(v)); return r;
}

// =====================================================================
// k_vec: s0[b,c] = Ct . w_c + bias ; s1[b,q] = Qt . w_q
// =====================================================================
__global__ void k_vec(const float* __restrict__ C, const float* __restrict__ Q,
                      const float* __restrict__ w_c, const float* __restrict__ w_q,
                      const float* __restrict__ bias) {
    __shared__ float w[128];
    int t = threadIdx.x;
    bool isQ = blockIdx.x >= 256;
    const float* W = isQ ? w_q : w_c;
    if (t < 128) w[t] = W[t];
    __syncthreads();
    if (!isQ) {
        int idx = blockIdx.x * 256 + t;           // b*LC + c
        int b = idx >> 11, c = idx & (LC_ - 1);
        const float* base = C + (size_t)b * D_ * LC_ + c;
        float acc = bias[0];
        #pragma unroll 8
        for (int dd = 0; dd < 128; dd++) acc += base[dd * LC_] * w[dd];
        g_s0[idx] = acc;
    } else {
        int idx = (blockIdx.x - 256) * 256 + t;   // b*LQ + q
        int b = idx >> 9, q = idx & (LQ_ - 1);
        const float* base = Q + (size_t)b * D_ * LQ_ + q;
        float acc = 0.f;
        #pragma unroll 8
        for (int dd = 0; dd < 128; dd++) acc += base[dd * LQ_] * w[dd];
        g_s1[idx] = acc;
    }
}

// =====================================================================
// k_S: E[b,c,q] = qmask[q] * exp( (Ct*w_mul) @ Qt^T + s0[c] + s1[q] )
// GEMM M=Lc N=Lq K=128, tile 128x128, K-chunk 32
// =====================================================================
__global__ void __launch_bounds__(256) k_S(const float* __restrict__ C,
                                           const float* __restrict__ Q,
                                           const float* __restrict__ w_mul,
                                           const int* __restrict__ Qmask) {
    __shared__ float As[32 * 132];   // [kk][m]  (Ct * w_mul)
    __shared__ float Bs[32 * 132];   // [kk][n]  (Qt)
    __shared__ float wm[128];
    int b = blockIdx.z;
    int cBase = blockIdx.y * 128, qBase = blockIdx.x * 128;
    int tid = threadIdx.x, tx = tid & 15, ty = tid >> 4;
    if (tid < 128) wm[tid] = w_mul[tid];
    __syncthreads();
    const float* Cb = C + (size_t)b * D_ * LC_;
    const float* Qb = Q + (size_t)b * D_ * LQ_;
    ull acc[8][4] = {};
    for (int k0 = 0; k0 < 128; k0 += 32) {
        #pragma unroll
        for (int p = 0; p < 16; p++) {
            int idx = tid + p * 256;
            int kk = idx >> 7, m = idx & 127;
            As[kk * 132 + m] = Cb[(k0 + kk) * LC_ + cBase + m] * wm[k0 + kk];
            Bs[kk * 132 + m] = Qb[(k0 + kk) * LQ_ + qBase + m];
        }
        __syncthreads();
        #pragma unroll
        for (int kk = 0; kk < 32; kk++) {
            float4 a0 = *(const float4*)&As[kk * 132 + ty * 4];
            float4 a1 = *(const float4*)&As[kk * 132 + 64 + ty * 4];
            ulonglong2 b0 = *(const ulonglong2*)&Bs[kk * 132 + tx * 4];
            ulonglong2 b1 = *(const ulonglong2*)&Bs[kk * 132 + 64 + tx * 4];
            ull av[8] = {pk2(a0.x), pk2(a0.y), pk2(a0.z), pk2(a0.w),
                         pk2(a1.x), pk2(a1.y), pk2(a1.z), pk2(a1.w)};
            ull bv[4] = {b0.x, b0.y, b1.x, b1.y};
            #pragma unroll
            for (int i = 0; i < 8; i++)
                #pragma unroll
                for (int j = 0; j < 4; j++) fma2(acc[i][j], av[i], bv[j]);
        }
        __syncthreads();
    }
    // epilogue: + s0 + s1, exp, qmask, store E
    float s0v[8];
    int rows[8];
    #pragma unroll
    for (int i = 0; i < 8; i++) {
        int r = (i < 4) ? ty * 4 + i : 64 + ty * 4 + (i - 4);
        rows[i] = cBase + r;
        s0v[i] = g_s0[b * LC_ + rows[i]];
    }
    float s1v[8]; int qmv[8];
    #pragma unroll
    for (int j = 0; j < 8; j++) {
        int qc = qBase + ((j < 4) ? tx * 4 + j : 64 + tx * 4 + (j - 4));
        s1v[j] = g_s1[b * LQ_ + qc];
        qmv[j] = Qmask[b * LQ_ + qc];
    }
    float* Eb = g_E + (size_t)b * LC_ * LQ_;
    #pragma unroll
    for (int i = 0; i < 8; i++) {
        float v[8];
        #pragma unroll
        for (int j = 0; j < 4; j++) {
            float2 p = up2(acc[i][j]);
            v[2 * j] = p.x; v[2 * j + 1] = p.y;
        }
        float w[8];
        #pragma unroll
        for (int j = 0; j < 8; j++)
            w[j] = qmv[j] ? __expf(v[j] + s0v[i] + s1v[j]) : 0.f;
        float* rowp = Eb + rows[i] * LQ_ + qBase;
        *(float4*)(rowp + tx * 4)      = make_float4(w[0], w[1], w[2], w[3]);
        *(float4*)(rowp + 64 + tx * 4) = make_float4(w[4], w[5], w[6], w[7]);
    }
}

// =====================================================================
// k_Z1: rZ1[b,c] = 1 / rowsum(E)   (one warp per row)
// =====================================================================
__global__ void k_Z1() {
    int row = blockIdx.x * 8 + (threadIdx.x >> 5);
    int lane = threadIdx.x & 31;
    const float* Er = g_E + (size_t)row * LQ_;
    float s = 0.f;
    #pragma unroll
    for (int i = 0; i < 16; i++) s += Er[lane + i * 32];
    #pragma unroll
    for (int o = 16; o; o >>= 1) s += __shfl_xor_sync(0xffffffffu, s, o);
    if (lane == 0) g_rZ1[row] = 1.f / s;
}

// =====================================================================
// k_Z2: rZ2[b,q] = 1 / max(sum_c cmask[c]*E[c,q], tiny)
// =====================================================================
__global__ void k_Z2(const int* __restrict__ Cmask) {
    int b = blockIdx.y;
    int q = blockIdx.x * 128 + (threadIdx.x & 127);
    int half = threadIdx.x >> 7;
    const float* Eb = g_E + (size_t)b * LC_ * LQ_;
    const int* cm = Cmask + b * LC_;
    float s = 0.f;
    int c0 = half * 1024;
    #pragma unroll 4
    for (int c = c0; c < c0 + 1024; c++) {
        if (cm[c]) s += Eb[(size_t)c * LQ_ + q];
    }
    __shared__ float red[256];
    red[threadIdx.x] = s;
    __syncthreads();
    if (threadIdx.x < 128) {
        float tot = red[threadIdx.x] + red[threadIdx.x + 128];
        g_rZ2[b * LQ_ + q] = 1.f / fmaxf(tot, 1e-30f);
    }
}

// =====================================================================
// k_T: T[b,q,dd] = rZ2[q] * sum_c (cm[c]*E[c,q]) * C[b,dd,c]
// GEMM M=Lq(tile 64) N=128 K=Lc(chunk 32)
// =====================================================================
__global__ void __launch_bounds__(256) k_T(const float* __restrict__ C,
                                           const int* __restrict__ Cmask) {
    __shared__ float As[32 * 68];    // [cc][qq<64]  masked E
    __shared__ float Bs[32 * 132];   // [cc][dd]     C (transposed store)
    int b = blockIdx.y;
    int qBase = blockIdx.x * 64;
    int tid = threadIdx.x, tx = tid & 15, ty = tid >> 4;
    const float* Eb = g_E + (size_t)b * LC_ * LQ_;
    const float* Cb = C + (size_t)b * D_ * LC_;
    const int* cm = Cmask + b * LC_;
    ull acc[4][4] = {};
    for (int c0 = 0; c0 < LC_; c0 += 32) {
        #pragma unroll
        for (int p = 0; p < 8; p++) {
            int idx = tid + p * 256;              // 2048 elems
            int cc = idx >> 6, qq = idx & 63;
            As[cc * 68 + qq] = cm[c0 + cc] ? Eb[(size_t)(c0 + cc) * LQ_ + qBase + qq] : 0.f;
        }
        #pragma unroll
        for (int p = 0; p < 16; p++) {
            int idx = tid + p * 256;              // 4096 elems
            int dd = idx >> 5, cc = idx & 31;
            Bs[cc * 132 + dd] = Cb[dd * LC_ + c0 + cc];
        }
        __syncthreads();
        #pragma unroll
        for (int kk = 0; kk < 32; kk++) {
            float4 a0 = *(const float4*)&As[kk * 68 + ty * 4];
            ulonglong2 b0 = *(const ulonglong2*)&Bs[kk * 132 + tx * 4];
            ulonglong2 b1 = *(const ulonglong2*)&Bs[kk * 132 + 64 + tx * 4];
            ull av[4] = {pk2(a0.x), pk2(a0.y), pk2(a0.z), pk2(a0.w)};
            ull bv[4] = {b0.x, b0.y, b1.x, b1.y};
            #pragma unroll
            for (int i = 0; i < 4; i++)
                #pragma unroll
                for (int j = 0; j < 4; j++) fma2(acc[i][j], av[i], bv[j]);
        }
        __syncthreads();
    }
    #pragma unroll
    for (int i = 0; i < 4; i++) {
        int q = qBase + ty * 4 + i;
        float rz = g_rZ2[b * LQ_ + q];
        float* Tr = g_T + (size_t)(b * LQ_ + q) * D_;
        #pragma unroll
        for (int j = 0; j < 4; j++) {
            float2 v = up2(acc[i][j]);
            int col = (j < 2) ? tx * 4 + 2 * j : 64 + tx * 4 + 2 * (j - 2);
            Tr[col]     = v.x * rz;
            Tr[col + 1] = v.y * rz;
        }
    }
}

// =====================================================================
// k_AB: fused  A = S1 @ Qt,  Bm = S1 @ T,  + full output assembly.
// GEMM M=128(c) K=Lq N=128+128, tile 128, K-chunk 32.
// =====================================================================
__global__ void __launch_bounds__(256, 1) k_AB(const float* __restrict__ C,
                                               const float* __restrict__ Q,
                                               float* __restrict__ out) {
    extern __shared__ float dyn[];
    float* As = dyn;                 // [32][132] E tile, [qq][cc] (transposed)
    float* Bq = dyn + 32 * 132;      // [32][132] Qt tile [qq][dd] (transposed)
    float* Bt = dyn + 2 * 32 * 132;  // [32][132] T  tile [qq][dd] (natural)
    int b = blockIdx.y;
    int cBase = blockIdx.x * 128;
    int tid = threadIdx.x, tx = tid & 15, ty = tid >> 4;
    const float* Eb = g_E + (size_t)b * LC_ * LQ_;
    const float* Qb = Q + (size_t)b * D_ * LQ_;
    const float* Tb = g_T + (size_t)b * LQ_ * D_;

    ull accA[8][4] = {}, accB[8][4] = {};
    for (int q0 = 0; q0 < LQ_; q0 += 32) {
        #pragma unroll
        for (int p = 0; p < 16; p++) {
            int idx = tid + p * 256;
            int ci = idx >> 5, qq = idx & 31;
            As[qq * 132 + ci] = Eb[(size_t)(cBase + ci) * LQ_ + q0 + qq];
        }
        #pragma unroll
        for (int p = 0; p < 16; p++) {
            int idx = tid + p * 256;
            int dd = idx >> 5, qq = idx & 31;
            Bq[qq * 132 + dd] = Qb[dd * LQ_ + q0 + qq];
        }
        #pragma unroll
        for (int p = 0; p < 16; p++) {
            int idx = tid + p * 256;
            int qq = idx >> 7, dd = idx & 127;
            Bt[qq * 132 + dd] = Tb[(q0 + qq) * D_ + dd];
        }
        __syncthreads();
        #pragma unroll 8
        for (int kk = 0; kk < 32; kk++) {
            float4 a0 = *(const float4*)&As[kk * 132 + ty * 4];
            float4 a1 = *(const float4*)&As[kk * 132 + 64 + ty * 4];
            ull av[8] = {pk2(a0.x), pk2(a0.y), pk2(a0.z), pk2(a0.w),
                         pk2(a1.x), pk2(a1.y), pk2(a1.z), pk2(a1.w)};
            ulonglong2 q0v = *(const ulonglong2*)&Bq[kk * 132 + tx * 4];
            ulonglong2 q1v = *(const ulonglong2*)&Bq[kk * 132 + 64 + tx * 4];
            ulonglong2 t0v = *(const ulonglong2*)&Bt[kk * 132 + tx * 4];
            ulonglong2 t1v = *(const ulonglong2*)&Bt[kk * 132 + 64 + tx * 4];
            ull bqv[4] = {q0v.x, q0v.y, q1v.x, q1v.y};
            ull btv[4] = {t0v.x, t0v.y, t1v.x, t1v.y};
            #pragma unroll
            for (int i = 0; i < 8; i++) {
                #pragma unroll
                for (int j = 0; j < 4; j++) {
                    fma2(accA[i][j], av[i], bqv[j]);
                    fma2(accB[i][j], av[i], btv[j]);
                }
            }
        }
        __syncthreads();
    }

    float rz[8]; int rloc[8];
    #pragma unroll
    for (int i = 0; i < 8; i++) {
        rloc[i] = (i < 4) ? ty * 4 + i : 64 + ty * 4 + (i - 4);
        rz[i] = g_rZ1[b * LC_ + cBase + rloc[i]];
    }
    float* stage = dyn;  // [128][129], overlaps GEMM buffers (post-sync)
    float* outb = out + (size_t)b * (4 * D_) * LC_;
    const float* Cb = C + (size_t)b * D_ * LC_;

    // ---- pass A: write sections 0 (C), 1 (A), 2 (C*A)
    #pragma unroll
    for (int i = 0; i < 8; i++)
        #pragma unroll
        for (int j = 0; j < 4; j++) {
            float2 v = up2(accA[i][j]);
            int col = (j < 2) ? tx * 4 + 2 * j : 64 + tx * 4 + 2 * (j - 2);
            stage[rloc[i] * 129 + col]     = v.x * rz[i];
            stage[rloc[i] * 129 + col + 1] = v.y * rz[i];
        }
    __syncthreads();
    for (int idx = tid; idx < 128 * 128; idx += 256) {
        int dd = idx >> 7, c = idx & 127;
        float a = stage[c * 129 + dd];
        float cv = Cb[dd * LC_ + cBase + c];
        outb[(size_t)dd * LC_ + cBase + c]            = cv;
        outb[(size_t)(128 + dd) * LC_ + cBase + c]    = a;
        outb[(size_t)(256 + dd) * LC_ + cBase + c]    = cv * a;
    }
    __syncthreads();
    // ---- pass B: write section 3 (C*Bm)
    #pragma unroll
    for (int i = 0; i < 8; i++)
        #pragma unroll
        for (int j = 0; j < 4; j++) {
            float2 v = up2(accB[i][j]);
            int col = (j < 2) ? tx * 4 + 2 * j : 64 + tx * 4 + 2 * (j - 2);
            stage[rloc[i] * 129 + col]     = v.x * rz[i];
            stage[rloc[i] * 129 + col + 1] = v.y * rz[i];
        }
    __syncthreads();
    for (int idx = tid; idx < 128 * 128; idx += 256) {
        int dd = idx >> 7, c = idx & 127;
        float bm = stage[c * 129 + dd];
        float cv = Cb[dd * LC_ + cBase + c];
        outb[(size_t)(384 + dd) * LC_ + cBase + c] = cv * bm;
    }
}

// =====================================================================
extern "C" void kernel_launch(void* const* d_in, const int* in_sizes, int n_in,
                              void* d_out, int out_size) {
    const float* C     = (const float*)d_in[0];
    const float* Q     = (const float*)d_in[1];
    const int*   Cmask = (const int*)  d_in[2];
    const int*   Qmask = (const int*)  d_in[3];
    const float* w_c   = (const float*)d_in[4];
    const float* w_q   = (const float*)d_in[5];
    const float* w_mul = (const float*)d_in[6];
    const float* bias  = (const float*)d_in[7];
    float* out = (float*)d_out;

    k_vec<<<320, 256>>>(C, Q, w_c, w_q, bias);
    k_S<<<dim3(4, 16, 32), 256>>>(C, Q, w_mul, Qmask);
    k_Z1<<<(B_ * LC_) / 8, 256>>>();
    k_Z2<<<dim3(4, 32), 256>>>(Cmask);
    k_T<<<dim3(8, 32), 256>>>(C, Cmask);

    const int dynBytes = 128 * 129 * 4;  // 66048 B (stage dominates)
    cudaFuncSetAttribute(k_AB, cudaFuncAttributeMaxDynamicSharedMemorySize, dynBytes);
    k_AB<<<dim3(16, 32), 256, dynBytes>>>(C, Q, out);
}

// round 6
// speedup vs baseline: 1.2530x; 1.2530x over previous
#include <cuda_runtime.h>
#include <cuda_bf16.h>
#include <cstdint>
#include <math.h>

#define B_   32
#define D_   128
#define LC_  2048
#define LQ_  512

typedef unsigned int u32;

// ---------------- scratch (device globals: no alloc allowed) ----------------
__device__ u32   g_Ehi[(size_t)B_ * LC_ * LQ_ / 2];   // E [c][q] bf16 hi plane (u32 = 2 q)
__device__ u32   g_Elo[(size_t)B_ * LC_ * LQ_ / 2];   // E [c][q] bf16 lo plane
__device__ float g_T[(size_t)B_ * LQ_ * D_];          // T [q][d] fp32 (8 MB)
__device__ float g_Z1p[B_ * LC_ * 4];                 // Z1 partials per q-tile

// ---------------- helpers ----------------
__device__ __forceinline__ u32 s2u(const void* p) {
    u32 a; asm("{ .reg .u64 t; cvta.to.shared.u64 t, %1; cvt.u32.u64 %0, t; }" : "=r"(a) : "l"(p));
    return a;
}
#define SWZ(x) ((u32)(x) ^ ((((u32)(x)) >> 3) & 0x70))

__device__ __forceinline__ void sts32(u32 a, u32 v)  { asm volatile("st.shared.b32 [%0], %1;" :: "r"(a), "r"(v)); }
__device__ __forceinline__ void sts16(u32 a, u32 v)  { asm volatile("st.shared.b16 [%0], %1;" :: "r"(a), "h"((unsigned short)v)); }

__device__ __forceinline__ void splt(float v, u32 &hi, u32 &lo) {
    __nv_bfloat16 h = __float2bfloat16(v);
    float hf = __bfloat162float(h);
    __nv_bfloat16 l = __float2bfloat16(v - hf);
    hi = (u32)__bfloat16_as_ushort(h);
    lo = (u32)__bfloat16_as_ushort(l);
}
__device__ __forceinline__ float bf2f(u32 x) {
    __nv_bfloat16 h = __ushort_as_bfloat16((unsigned short)x);
    return __bfloat162float(h);
}

__device__ __forceinline__ void ldsm4(u32 addr, u32 &r0, u32 &r1, u32 &r2, u32 &r3) {
    asm volatile("ldmatrix.sync.aligned.m8n8.x4.shared.b16 {%0,%1,%2,%3}, [%4];"
                 : "=r"(r0), "=r"(r1), "=r"(r2), "=r"(r3) : "r"(addr));
}
__device__ __forceinline__ void hmma(float d[4], const u32 a[4], u32 b0, u32 b1) {
    asm volatile("mma.sync.aligned.m16n8k16.row.col.f32.bf16.bf16.f32 "
                 "{%0,%1,%2,%3}, {%4,%5,%6,%7}, {%8,%9}, {%0,%1,%2,%3};"
                 : "+f"(d[0]), "+f"(d[1]), "+f"(d[2]), "+f"(d[3])
                 : "r"(a[0]), "r"(a[1]), "r"(a[2]), "r"(a[3]), "r"(b0), "r"(b1));
}
// A-fragment ldmatrix address (16x16 tile at (m0,k0) of a [rows][64k bf16] SW-row panel)
__device__ __forceinline__ u32 aAddr(u32 base, int m0, int k0, int lane) {
    int r  = m0 + (lane & 15);
    int kc = k0 + ((lane >> 4) << 3);
    return base + SWZ(r * 128 + kc * 2);
}
// B-fragment ldmatrix address: loads two n8k16 tiles (n0, n0+8)
__device__ __forceinline__ u32 bAddr(u32 base, int n0, int k0, int lane) {
    int r  = n0 + (lane & 7) + ((lane & 16) ? 8 : 0);
    int kc = k0 + ((lane & 8) ? 8 : 0);
    return base + SWZ(r * 128 + kc * 2);
}

// Shared 64x(m64,n32) warp MMA step over one [128][64] limb-panel pair set.
// Ah/Al: A hi/lo panel bases; Bh/Bl: B hi/lo panel bases. 4 k-steps of 16.
__device__ __forceinline__ void mma_chunk64(float acc[4][4][4],
                                            u32 Ah, u32 Al, u32 Bh, u32 Bl,
                                            int m0w, int n0w, int lane) {
    #pragma unroll
    for (int ks = 0; ks < 4; ks++) {
        int k0 = ks * 16;
        u32 ah[4][4], al[4][4], bh[4][2], bl[4][2];
        #pragma unroll
        for (int mi = 0; mi < 4; mi++) {
            ldsm4(aAddr(Ah, m0w + mi * 16, k0, lane), ah[mi][0], ah[mi][1], ah[mi][2], ah[mi][3]);
            ldsm4(aAddr(Al, m0w + mi * 16, k0, lane), al[mi][0], al[mi][1], al[mi][2], al[mi][3]);
        }
        #pragma unroll
        for (int nj2 = 0; nj2 < 2; nj2++) {
            u32 t0, t1, t2, t3;
            ldsm4(bAddr(Bh, n0w + nj2 * 16, k0, lane), t0, t1, t2, t3);
            bh[nj2 * 2][0] = t0; bh[nj2 * 2][1] = t1; bh[nj2 * 2 + 1][0] = t2; bh[nj2 * 2 + 1][1] = t3;
            ldsm4(bAddr(Bl, n0w + nj2 * 16, k0, lane), t0, t1, t2, t3);
            bl[nj2 * 2][0] = t0; bl[nj2 * 2][1] = t1; bl[nj2 * 2 + 1][0] = t2; bl[nj2 * 2 + 1][1] = t3;
        }
        #pragma unroll
        for (int mi = 0; mi < 4; mi++)
            #pragma unroll
            for (int nj = 0; nj < 4; nj++) {
                hmma(acc[mi][nj], ah[mi], bh[nj][0], bh[nj][1]);
                hmma(acc[mi][nj], ah[mi], bl[nj][0], bl[nj][1]);
                hmma(acc[mi][nj], al[mi], bh[nj][0], bh[nj][1]);
            }
    }
}

// =====================================================================
// k_S: E = qmask*exp(S), S = (Ct*wm)@Qt^T + s0 + s1 + bias.
//   M=128(c) x N=128(q), K=128(d). s0/s1 from loaders; Z1 partials out.
// =====================================================================
#define KS_WC 0
#define KS_WQ 512
#define KS_WM 1024
#define KS_S0 1536
#define KS_S1 2048
#define KS_QM 2560
#define KS_ZS 3072      // 512 floats
#define KS_A  8192      // hi p0, hi p1, lo p0, lo p1 : 4*16KB
#define KS_B  73728     // same
#define KS_DYN 139264

__global__ void __launch_bounds__(256, 1) k_S(const float* __restrict__ C,
                                              const float* __restrict__ Q,
                                              const float* __restrict__ w_c,
                                              const float* __restrict__ w_q,
                                              const float* __restrict__ w_mul,
                                              const float* __restrict__ bias,
                                              const int* __restrict__ Qmask) {
    extern __shared__ char sm[];
    u32 sb = s2u(sm);
    int tid = threadIdx.x, lane = tid & 31, wid = tid >> 5;
    int b = blockIdx.z, cB = blockIdx.y * 128, qB = blockIdx.x * 128, qt = blockIdx.x;

    float* wcf = (float*)(sm + KS_WC);
    float* wqf = (float*)(sm + KS_WQ);
    float* wmf = (float*)(sm + KS_WM);
    float* s0f = (float*)(sm + KS_S0);
    float* s1f = (float*)(sm + KS_S1);
    int*   qmi = (int*)(sm + KS_QM);
    float* zs  = (float*)(sm + KS_ZS);

    if (tid < 128) {
        wcf[tid] = w_c[tid]; wqf[tid] = w_q[tid]; wmf[tid] = w_mul[tid];
        qmi[tid] = Qmask[b * LQ_ + qB + tid];
    }
    __syncthreads();

    const float* Cb = C + (size_t)b * D_ * LC_ + cB;
    const float* Qb = Q + (size_t)b * D_ * LQ_ + qB;

    // A: (Ct*wm)[c][d] panels, + s0 partials (c = tid&127 fixed)
    float s0p = 0.f;
    #pragma unroll 4
    for (int i = 0; i < 32; i++) {
        int idx = tid + i * 256;
        int c = idx & 127, j = idx >> 7;
        float v0 = Cb[(size_t)(2 * j) * LC_ + c];
        float v1 = Cb[(size_t)(2 * j + 1) * LC_ + c];
        s0p += v0 * wcf[2 * j] + v1 * wcf[2 * j + 1];
        u32 h0, l0, h1, l1;
        splt(v0 * wmf[2 * j], h0, l0);
        splt(v1 * wmf[2 * j + 1], h1, l1);
        u32 off = SWZ(c * 128 + (j & 31) * 4);
        u32 pb = sb + KS_A + (j >> 5) * 16384;
        sts32(pb + off, h0 | (h1 << 16));
        sts32(pb + 32768 + off, l0 | (l1 << 16));
    }
    zs[tid] = s0p;
    // B: Qt[q][d] panels, + s1 partials (q = tid&127 fixed)
    float s1p = 0.f;
    #pragma unroll 4
    for (int i = 0; i < 32; i++) {
        int idx = tid + i * 256;
        int q = idx & 127, j = idx >> 7;
        float v0 = Qb[(size_t)(2 * j) * LQ_ + q];
        float v1 = Qb[(size_t)(2 * j + 1) * LQ_ + q];
        s1p += v0 * wqf[2 * j] + v1 * wqf[2 * j + 1];
        u32 h0, l0, h1, l1;
        splt(v0, h0, l0);
        splt(v1, h1, l1);
        u32 off = SWZ(q * 128 + (j & 31) * 4);
        u32 pb = sb + KS_B + (j >> 5) * 16384;
        sts32(pb + off, h0 | (h1 << 16));
        sts32(pb + 32768 + off, l0 | (l1 << 16));
    }
    zs[256 + tid] = s1p;
    __syncthreads();
    if (tid < 128) s0f[tid] = zs[tid] + zs[tid + 128] + bias[0];
    else { int q = tid - 128; s1f[q] = zs[256 + q] + zs[256 + q + 128]; }

    int wm = wid >> 2, wn = wid & 3;
    int m0w = wm * 64, n0w = wn * 32;
    float acc[4][4][4] = {};
    #pragma unroll
    for (int p = 0; p < 2; p++) {
        u32 Ah = sb + KS_A + p * 16384, Al = Ah + 32768;
        u32 Bh = sb + KS_B + p * 16384, Bl = Bh + 32768;
        mma_chunk64(acc, Ah, Al, Bh, Bl, m0w, n0w, lane);
    }
    __syncthreads();   // s0f/s1f visible; zs free for Z1 partials

    int r = lane >> 2, cp = (lane & 3) * 2;
    float zrow[8] = {};
    size_t Ebase = ((size_t)b * LC_ + cB) * LQ_ + qB;
    #pragma unroll
    for (int mi = 0; mi < 4; mi++) {
        int m0 = m0w + mi * 16 + r;
        float s0a = s0f[m0], s0b = s0f[m0 + 8];
        #pragma unroll
        for (int nj = 0; nj < 4; nj++) {
            int q0 = n0w + nj * 8 + cp;
            float s1a = s1f[q0], s1b = s1f[q0 + 1];
            int qa = qmi[q0], qb = qmi[q0 + 1];
            float e00 = qa ? __expf(acc[mi][nj][0] + s0a + s1a) : 0.f;
            float e01 = qb ? __expf(acc[mi][nj][1] + s0a + s1b) : 0.f;
            float e10 = qa ? __expf(acc[mi][nj][2] + s0b + s1a) : 0.f;
            float e11 = qb ? __expf(acc[mi][nj][3] + s0b + s1b) : 0.f;
            zrow[mi * 2]     += e00 + e01;
            zrow[mi * 2 + 1] += e10 + e11;
            u32 h00, l00, h01_, l01_, h10, l10, h11, l11;
            splt(e00, h00, l00); splt(e01, h01_, l01_);
            splt(e10, h10, l10); splt(e11, h11, l11);
            size_t i0 = (Ebase + (size_t)m0 * LQ_ + q0) >> 1;
            size_t i1 = (Ebase + (size_t)(m0 + 8) * LQ_ + q0) >> 1;
            g_Ehi[i0] = h00 | (h01_ << 16);
            g_Elo[i0] = l00 | (l01_ << 16);
            g_Ehi[i1] = h10 | (h11 << 16);
            g_Elo[i1] = l10 | (l11 << 16);
        }
    }
    #pragma unroll
    for (int h = 0; h < 8; h++) {
        float v = zrow[h];
        v += __shfl_xor_sync(0xffffffffu, v, 1);
        v += __shfl_xor_sync(0xffffffffu, v, 2);
        if ((lane & 3) == 0) {
            int m = m0w + (h >> 1) * 16 + ((h & 1) ? 8 : 0) + r;
            zs[m * 4 + wn] = v;
        }
    }
    __syncthreads();
    if (tid < 128)
        g_Z1p[((size_t)b * LC_ + cB + tid) * 4 + qt] =
            zs[tid * 4] + zs[tid * 4 + 1] + zs[tid * 4 + 2] + zs[tid * 4 + 3];
}

// =====================================================================
// k_T: T[q][d] = rZ2[q] * sum_c cm[c]*E[c,q]*C[d,c].
//   M=128(q) x N=128(d), K=2048(c) in 32 chunks of 64. Z2 from A-loader.
// =====================================================================
#define KT_ZS 0         // 512 floats
#define KT_RZ 2048      // 128 floats
#define KT_A  4096      // hi, lo : 2*16KB
#define KT_B  36864     // hi, lo
#define KT_DYN 69632

__global__ void __launch_bounds__(256, 1) k_T(const float* __restrict__ C,
                                              const int* __restrict__ Cmask) {
    extern __shared__ char sm[];
    u32 sb = s2u(sm);
    int tid = threadIdx.x, lane = tid & 31, wid = tid >> 5;
    int b = blockIdx.y, qB = blockIdx.x * 128;
    const float* Cb = C + (size_t)b * D_ * LC_;
    const int* cmg = Cmask + b * LC_;
    size_t Ebase = ((size_t)b * LC_) * LQ_ + qB;

    int wm = wid >> 2, wn = wid & 3;
    int m0w = wm * 64, n0w = wn * 32;
    float acc[4][4][4] = {};
    float z0 = 0.f, z1 = 0.f;
    int jq = tid & 63;                 // fixed q-pair per thread

    for (int ci = 0; ci < 32; ci++) {
        int c0 = ci * 64;
        __syncthreads();               // prior MMA done; panels free
        // A: E^T (masked) -> [q][c] panels; Z2 partials
        #pragma unroll 4
        for (int i = 0; i < 16; i++) {
            int c = (tid >> 6) + 4 * i;
            size_t gi = (Ebase + (size_t)(c0 + c) * LQ_ + 2 * jq) >> 1;
            u32 h01 = g_Ehi[gi], l01 = g_Elo[gi];
            int cm = cmg[c0 + c];
            if (!cm) { h01 = 0; l01 = 0; }
            else {
                z0 += bf2f(h01 & 0xffff) + bf2f(l01 & 0xffff);
                z1 += bf2f(h01 >> 16)    + bf2f(l01 >> 16);
            }
            u32 o0 = SWZ((2 * jq) * 128 + c * 2);
            u32 o1 = SWZ((2 * jq + 1) * 128 + c * 2);
            sts16(sb + KT_A + o0, h01 & 0xffff);
            sts16(sb + KT_A + o1, h01 >> 16);
            sts16(sb + KT_A + 16384 + o0, l01 & 0xffff);
            sts16(sb + KT_A + 16384 + o1, l01 >> 16);
        }
        // B: C[d][c] natural panels
        #pragma unroll 4
        for (int i = 0; i < 16; i++) {
            int idx = tid + i * 256;
            int jc = idx & 31, d = idx >> 5;
            float2 v = *(const float2*)&Cb[(size_t)d * LC_ + c0 + 2 * jc];
            u32 h0, l0, h1, l1;
            splt(v.x, h0, l0); splt(v.y, h1, l1);
            u32 off = SWZ(d * 128 + jc * 4);
            sts32(sb + KT_B + off, h0 | (h1 << 16));
            sts32(sb + KT_B + 16384 + off, l0 | (l1 << 16));
        }
        __syncthreads();
        mma_chunk64(acc, sb + KT_A, sb + KT_A + 16384,
                         sb + KT_B, sb + KT_B + 16384, m0w, n0w, lane);
    }
    float* zs = (float*)(sm + KT_ZS);
    float* rzs = (float*)(sm + KT_RZ);
    __syncthreads();
    zs[tid * 2] = z0; zs[tid * 2 + 1] = z1;
    __syncthreads();
    if (tid < 128) {
        int q = tid, j = q >> 1, par = q & 1;
        float s = zs[(0 * 64 + j) * 2 + par] + zs[(1 * 64 + j) * 2 + par]
                + zs[(2 * 64 + j) * 2 + par] + zs[(3 * 64 + j) * 2 + par];
        rzs[q] = 1.f / fmaxf(s, 1e-30f);
    }
    __syncthreads();

    int r = lane >> 2, cp = (lane & 3) * 2;
    #pragma unroll
    for (int mi = 0; mi < 4; mi++) {
        int m0 = m0w + mi * 16 + r;
        float rza = rzs[m0], rzb = rzs[m0 + 8];
        #pragma unroll
        for (int nj = 0; nj < 4; nj++) {
            int d0 = n0w + nj * 8 + cp;
            float* t0 = &g_T[((size_t)(b * LQ_ + qB + m0)) * D_ + d0];
            float* t1 = &g_T[((size_t)(b * LQ_ + qB + m0 + 8)) * D_ + d0];
            *(float2*)t0 = make_float2(acc[mi][nj][0] * rza, acc[mi][nj][1] * rza);
            *(float2*)t1 = make_float2(acc[mi][nj][2] * rzb, acc[mi][nj][3] * rzb);
        }
    }
}

// =====================================================================
// k_AB: mode 0: D = E@Qt (-> sections 0,1,2); mode 1: D = E@T (-> section 3).
//   M=128(c) x N=128(d), K=512(q) in 8 chunks of 64. rZ1 applied.
// =====================================================================
#define KA_RZ 0         // 128 floats
#define KA_A  1024      // hi, lo
#define KA_B  33792     // hi, lo
#define KA_STG 66560    // 128*132 floats
#define KA_DYN 134144

__global__ void __launch_bounds__(256, 1) k_AB(const float* __restrict__ C,
                                               const float* __restrict__ Q,
                                               float* __restrict__ out) {
    extern __shared__ char sm[];
    u32 sb = s2u(sm);
    int tid = threadIdx.x, lane = tid & 31, wid = tid >> 5;
    int b = blockIdx.y, cB = blockIdx.x * 128, mode = blockIdx.z;
    const float* Qb = Q + (size_t)b * D_ * LQ_;
    const float* Tb = g_T + (size_t)b * LQ_ * D_;
    size_t Ebase = ((size_t)b * LC_ + cB) * LQ_;

    int wm = wid >> 2, wn = wid & 3;
    int m0w = wm * 64, n0w = wn * 32;
    float acc[4][4][4] = {};

    for (int ci = 0; ci < 8; ci++) {
        int q0 = ci * 64;
        __syncthreads();
        // A: E[c][q] natural panels (no convert: planes are already limbs)
        #pragma unroll 4
        for (int i = 0; i < 16; i++) {
            int idx = tid + i * 256;
            int jq = idx & 31, c = idx >> 5;
            size_t gi = (Ebase + (size_t)c * LQ_ + q0 + 2 * jq) >> 1;
            u32 off = SWZ(c * 128 + jq * 4);
            sts32(sb + KA_A + off, g_Ehi[gi]);
            sts32(sb + KA_A + 16384 + off, g_Elo[gi]);
        }
        // B panels
        if (mode == 0) {
            #pragma unroll 4
            for (int i = 0; i < 16; i++) {
                int idx = tid + i * 256;
                int jq = idx & 31, d = idx >> 5;
                float2 v = *(const float2*)&Qb[(size_t)d * LQ_ + q0 + 2 * jq];
                u32 h0, l0, h1, l1;
                splt(v.x, h0, l0); splt(v.y, h1, l1);
                u32 off = SWZ(d * 128 + jq * 4);
                sts32(sb + KA_B + off, h0 | (h1 << 16));
                sts32(sb + KA_B + 16384 + off, l0 | (l1 << 16));
            }
        } else {
            #pragma unroll 4
            for (int i = 0; i < 16; i++) {
                int idx = tid + i * 256;
                int d = idx & 127, jq = idx >> 7;
                float v0 = Tb[(size_t)(q0 + 2 * jq) * D_ + d];
                float v1 = Tb[(size_t)(q0 + 2 * jq + 1) * D_ + d];
                u32 h0, l0, h1, l1;
                splt(v0, h0, l0); splt(v1, h1, l1);
                u32 off = SWZ(d * 128 + jq * 4);
                sts32(sb + KA_B + off, h0 | (h1 << 16));
                sts32(sb + KA_B + 16384 + off, l0 | (l1 << 16));
            }
        }
        __syncthreads();
        mma_chunk64(acc, sb + KA_A, sb + KA_A + 16384,
                         sb + KA_B, sb + KA_B + 16384, m0w, n0w, lane);
    }
    __syncthreads();
    float* rzs = (float*)(sm + KA_RZ);
    if (tid < 128) {
        const float* p = &g_Z1p[((size_t)b * LC_ + cB + tid) * 4];
        rzs[tid] = 1.f / (p[0] + p[1] + p[2] + p[3]);
    }
    __syncthreads();

    // stage [d][c] (pitch 132) with rZ1 applied
    float* stg = (float*)(sm + KA_STG);
    int r = lane >> 2, cp = (lane & 3) * 2;
    #pragma unroll
    for (int mi = 0; mi < 4; mi++) {
        int m0 = m0w + mi * 16 + r;
        float rza = rzs[m0], rzb = rzs[m0 + 8];
        #pragma unroll
        for (int nj = 0; nj < 4; nj++) {
            int n0 = n0w + nj * 8 + cp;
            stg[n0 * 132 + m0]           = acc[mi][nj][0] * rza;
            stg[(n0 + 1) * 132 + m0]     = acc[mi][nj][1] * rza;
            stg[n0 * 132 + m0 + 8]       = acc[mi][nj][2] * rzb;
            stg[(n0 + 1) * 132 + m0 + 8] = acc[mi][nj][3] * rzb;
        }
    }
    __syncthreads();
    const float* Cb = C + (size_t)b * D_ * LC_ + cB;
    float* ob = out + (size_t)b * 4 * D_ * LC_ + cB;
    if (mode == 0) {
        for (int idx = tid; idx < 128 * 128; idx += 256) {
            int dd = idx >> 7, c = idx & 127;
            float a = stg[dd * 132 + c];
            float cv = Cb[(size_t)dd * LC_ + c];
            ob[(size_t)dd * LC_ + c]         = cv;
            ob[(size_t)(128 + dd) * LC_ + c] = a;
            ob[(size_t)(256 + dd) * LC_ + c] = cv * a;
        }
    } else {
        for (int idx = tid; idx < 128 * 128; idx += 256) {
            int dd = idx >> 7, c = idx & 127;
            float bm = stg[dd * 132 + c];
            float cv = Cb[(size_t)dd * LC_ + c];
            ob[(size_t)(384 + dd) * LC_ + c] = cv * bm;
        }
    }
}

// =====================================================================
extern "C" void kernel_launch(void* const* d_in, const int* in_sizes, int n_in,
                              void* d_out, int out_size) {
    const float* C     = (const float*)d_in[0];
    const float* Q     = (const float*)d_in[1];
    const int*   Cmask = (const int*)  d_in[2];
    const int*   Qmask = (const int*)  d_in[3];
    const float* w_c   = (const float*)d_in[4];
    const float* w_q   = (const float*)d_in[5];
    const float* w_mul = (const float*)d_in[6];
    const float* bias  = (const float*)d_in[7];
    float* out = (float*)d_out;

    cudaFuncSetAttribute(k_S,  cudaFuncAttributeMaxDynamicSharedMemorySize, KS_DYN);
    cudaFuncSetAttribute(k_T,  cudaFuncAttributeMaxDynamicSharedMemorySize, KT_DYN);
    cudaFuncSetAttribute(k_AB, cudaFuncAttributeMaxDynamicSharedMemorySize, KA_DYN);

    k_S<<<dim3(4, 16, 32), 256, KS_DYN>>>(C, Q, w_c, w_q, w_mul, bias, Qmask);
    k_T<<<dim3(4, 32), 256, KT_DYN>>>(C, Cmask);
    k_AB<<<dim3(16, 32, 2), 256, KA_DYN>>>(C, Q, out);
}

// round 7
// speedup vs baseline: 2.8551x; 2.2785x over previous
#include <cuda_runtime.h>
#include <cuda_bf16.h>
#include <cstdint>

#define B_   32
#define D_   128
#define LC_  2048
#define LQ_  512

typedef unsigned int u32;

// ---------------- scratch planes (bf16 hi/lo stored as u32 pairs) ----------
__device__ u32 g_Ehi[(size_t)B_ * LC_ * LQ_ / 2];
__device__ u32 g_Elo[(size_t)B_ * LC_ * LQ_ / 2];
__device__ u32 g_Cwhi[(size_t)B_ * D_ * LC_ / 2];
__device__ u32 g_Cwlo[(size_t)B_ * D_ * LC_ / 2];
__device__ u32 g_Cmhi[(size_t)B_ * D_ * LC_ / 2];
__device__ u32 g_Cmlo[(size_t)B_ * D_ * LC_ / 2];
__device__ u32 g_Qhi[(size_t)B_ * D_ * LQ_ / 2];
__device__ u32 g_Qlo[(size_t)B_ * D_ * LQ_ / 2];
__device__ u32 g_Thi[(size_t)B_ * LQ_ * D_ / 2];
__device__ u32 g_Tlo[(size_t)B_ * LQ_ * D_ / 2];
__device__ float g_s0[B_ * LC_];
__device__ float g_s1[B_ * LQ_];
__device__ float g_Z1p[B_ * LC_ * 4];
__device__ float g_Z2p[B_ * LQ_ * 16];

// ---------------- helpers ----------------
__device__ __forceinline__ u32 s2u(const void* p) {
    u32 a; asm("{ .reg .u64 t; cvta.to.shared.u64 t, %1; cvt.u32.u64 %0, t; }" : "=r"(a) : "l"(p));
    return a;
}
#define SWZ(x) ((u32)(x) ^ ((((u32)(x)) >> 3) & 0x70))

__device__ __forceinline__ void cpa16(u32 dst, const void* src) {
    asm volatile("cp.async.cg.shared.global [%0], [%1], 16;" :: "r"(dst), "l"(src));
}
#define CP_COMMIT() asm volatile("cp.async.commit_group;")
#define CP_WAIT0()  asm volatile("cp.async.wait_group 0;")
#define CP_WAIT1()  asm volatile("cp.async.wait_group 1;")

__device__ __forceinline__ void splt(float v, u32 &hi, u32 &lo) {
    __nv_bfloat16 h = __float2bfloat16(v);
    float hf = __bfloat162float(h);
    __nv_bfloat16 l = __float2bfloat16(v - hf);
    hi = (u32)__bfloat16_as_ushort(h);
    lo = (u32)__bfloat16_as_ushort(l);
}

__device__ __forceinline__ void ldsm4(u32 addr, u32 r[4]) {
    asm volatile("ldmatrix.sync.aligned.m8n8.x4.shared.b16 {%0,%1,%2,%3}, [%4];"
                 : "=r"(r[0]), "=r"(r[1]), "=r"(r[2]), "=r"(r[3]) : "r"(addr));
}
__device__ __forceinline__ void ldsm4t(u32 addr, u32 r[4]) {
    asm volatile("ldmatrix.sync.aligned.m8n8.x4.trans.shared.b16 {%0,%1,%2,%3}, [%4];"
                 : "=r"(r[0]), "=r"(r[1]), "=r"(r[2]), "=r"(r[3]) : "r"(addr));
}
__device__ __forceinline__ void hmma(float d[4], const u32 a[4], u32 b0, u32 b1) {
    asm volatile("mma.sync.aligned.m16n8k16.row.col.f32.bf16.bf16.f32 "
                 "{%0,%1,%2,%3}, {%4,%5,%6,%7}, {%8,%9}, {%0,%1,%2,%3};"
                 : "+f"(d[0]), "+f"(d[1]), "+f"(d[2]), "+f"(d[3])
                 : "r"(a[0]), "r"(a[1]), "r"(a[2]), "r"(a[3]), "r"(b0), "r"(b1));
}

// ---------------- chunk copy (pure cp.async, 64KB per chunk) --------------
// R64: rows = k (64), cols = 128 (two 8KB col-panels); limb lo at +16384
__device__ __forceinline__ void cpyR64(u32 dstBase, const __nv_bfloat16* srcHi,
                                       const __nv_bfloat16* srcLo, size_t rowStride, int tid) {
    #pragma unroll
    for (int t = 0; t < 8; t++) {
        int u = tid + t * 256;
        int limb = u >> 10, rem = u & 1023;
        int row = rem >> 4, ucol = rem & 15;
        const __nv_bfloat16* src = (limb ? srcLo : srcHi) + (size_t)row * rowStride + ucol * 8;
        u32 dst = dstBase + limb * 16384 + (ucol >> 3) * 8192 + SWZ(row * 128 + (ucol & 7) * 16);
        cpa16(dst, src);
    }
}
// R128: rows = m/n (128), cols = k (64); limb lo at +16384
__device__ __forceinline__ void cpyR128(u32 dstBase, const __nv_bfloat16* srcHi,
                                        const __nv_bfloat16* srcLo, size_t rowStride, int tid) {
    #pragma unroll
    for (int t = 0; t < 8; t++) {
        int u = tid + t * 256;
        int limb = u >> 10, rem = u & 1023;
        int row = rem >> 3, ucol = rem & 7;
        const __nv_bfloat16* src = (limb ? srcLo : srcHi) + (size_t)row * rowStride + ucol * 8;
        u32 dst = dstBase + limb * 16384 + SWZ(row * 128 + ucol * 16);
        cpa16(dst, src);
    }
}

// ---------------- warp MMA over one k=64 chunk (3-limb) -------------------
// AT/BT: operand stored K-major (rows=k) -> trans ldmatrix
template<int AT, int BT>
__device__ __forceinline__ void mma_chunk(float acc[4][4][4], u32 Ab, u32 Bb,
                                          int m0w, int n0w, int lane) {
    #pragma unroll
    for (int ks = 0; ks < 4; ks++) {
        int k0 = ks * 16;
        u32 ah[4][4], al[4][4];
        #pragma unroll
        for (int mi = 0; mi < 4; mi++) {
            int m0 = m0w + mi * 16;
            u32 ad;
            if (AT) {
                int r = k0 + (lane & 7) + ((lane & 16) ? 8 : 0);
                int c = m0 + ((lane & 8) ? 8 : 0);
                ad = Ab + ((u32)(c >> 6)) * 8192 + SWZ(r * 128 + (c & 63) * 2);
                ldsm4t(ad, ah[mi]); ldsm4t(ad + 16384, al[mi]);
            } else {
                int r = m0 + (lane & 15);
                int c = k0 + ((lane >> 4) << 3);
                ad = Ab + SWZ(r * 128 + c * 2);
                ldsm4(ad, ah[mi]); ldsm4(ad + 16384, al[mi]);
            }
        }
        u32 bh[4][2], bl[4][2];
        #pragma unroll
        for (int nj2 = 0; nj2 < 2; nj2++) {
            int n0 = n0w + nj2 * 16;
            u32 bd;
            u32 t[4], tl[4];
            if (BT) {
                int r = k0 + (lane & 7) + ((lane & 8) ? 8 : 0);
                int c = n0 + ((lane & 16) ? 8 : 0);
                bd = Bb + ((u32)(c >> 6)) * 8192 + SWZ(r * 128 + (c & 63) * 2);
                ldsm4t(bd, t); ldsm4t(bd + 16384, tl);
            } else {
                int r = n0 + (lane & 7) + ((lane & 16) ? 8 : 0);
                int c = k0 + ((lane & 8) ? 8 : 0);
                bd = Bb + SWZ(r * 128 + c * 2);
                ldsm4(bd, t); ldsm4(bd + 16384, tl);
            }
            bh[nj2 * 2][0] = t[0];  bh[nj2 * 2][1] = t[1];
            bh[nj2 * 2 + 1][0] = t[2]; bh[nj2 * 2 + 1][1] = t[3];
            bl[nj2 * 2][0] = tl[0]; bl[nj2 * 2][1] = tl[1];
            bl[nj2 * 2 + 1][0] = tl[2]; bl[nj2 * 2 + 1][1] = tl[3];
        }
        #pragma unroll
        for (int mi = 0; mi < 4; mi++)
            #pragma unroll
            for (int nj = 0; nj < 4; nj++) {
                hmma(acc[mi][nj], ah[mi], bh[nj][0], bh[nj][1]);
                hmma(acc[mi][nj], ah[mi], bl[nj][0], bl[nj][1]);
                hmma(acc[mi][nj], al[mi], bh[nj][0], bh[nj][1]);
            }
    }
}

// =====================================================================
// k_cvtC: C fp32 -> Cw (=C*w_mul) and Cm (=C*cmask) limb planes
// =====================================================================
__global__ void k_cvtC(const float* __restrict__ C, const int* __restrict__ Cmask,
                       const float* __restrict__ w_mul) {
    size_t idx = (size_t)blockIdx.x * 256 + threadIdx.x;
    size_t g4 = idx * 4;
    int c = (int)(g4 & (LC_ - 1));
    int d = (int)((g4 >> 11) & (D_ - 1));
    int b = (int)(g4 >> 18);
    float4 v = *(const float4*)(C + g4);
    int4 m = *(const int4*)(Cmask + b * LC_ + c);
    float w = w_mul[d];
    u32 h[4], l[4];
    splt(v.x * w, h[0], l[0]); splt(v.y * w, h[1], l[1]);
    splt(v.z * w, h[2], l[2]); splt(v.w * w, h[3], l[3]);
    ((uint2*)g_Cwhi)[idx] = make_uint2(h[0] | (h[1] << 16), h[2] | (h[3] << 16));
    ((uint2*)g_Cwlo)[idx] = make_uint2(l[0] | (l[1] << 16), l[2] | (l[3] << 16));
    splt(m.x ? v.x : 0.f, h[0], l[0]); splt(m.y ? v.y : 0.f, h[1], l[1]);
    splt(m.z ? v.z : 0.f, h[2], l[2]); splt(m.w ? v.w : 0.f, h[3], l[3]);
    ((uint2*)g_Cmhi)[idx] = make_uint2(h[0] | (h[1] << 16), h[2] | (h[3] << 16));
    ((uint2*)g_Cmlo)[idx] = make_uint2(l[0] | (l[1] << 16), l[2] | (l[3] << 16));
}

// =====================================================================
// k_cvtQ: Q fp32 -> limb planes
// =====================================================================
__global__ void k_cvtQ(const float* __restrict__ Q) {
    size_t idx = (size_t)blockIdx.x * 256 + threadIdx.x;
    float4 v = *(const float4*)(Q + idx * 4);
    u32 h[4], l[4];
    splt(v.x, h[0], l[0]); splt(v.y, h[1], l[1]);
    splt(v.z, h[2], l[2]); splt(v.w, h[3], l[3]);
    ((uint2*)g_Qhi)[idx] = make_uint2(h[0] | (h[1] << 16), h[2] | (h[3] << 16));
    ((uint2*)g_Qlo)[idx] = make_uint2(l[0] | (l[1] << 16), l[2] | (l[3] << 16));
}

// =====================================================================
// k_vec: s0[b,c] = Ct.w_c + bias ; s1[b,q] = Qt.w_q  (fp32 exact)
// =====================================================================
__global__ void k_vec(const float* __restrict__ C, const float* __restrict__ Q,
                      const float* __restrict__ w_c, const float* __restrict__ w_q,
                      const float* __restrict__ bias) {
    __shared__ float w[128];
    int t = threadIdx.x;
    bool isQ = blockIdx.x >= 256;
    const float* W = isQ ? w_q : w_c;
    if (t < 128) w[t] = W[t];
    __syncthreads();
    if (!isQ) {
        int idx = blockIdx.x * 256 + t;
        int b = idx >> 11, c = idx & (LC_ - 1);
        const float* base = C + (size_t)b * D_ * LC_ + c;
        float acc = bias[0];
        #pragma unroll 8
        for (int dd = 0; dd < 128; dd++) acc += base[dd * LC_] * w[dd];
        g_s0[idx] = acc;
    } else {
        int idx = (blockIdx.x - 256) * 256 + t;
        int b = idx >> 9, q = idx & (LQ_ - 1);
        const float* base = Q + (size_t)b * D_ * LQ_ + q;
        float acc = 0.f;
        #pragma unroll 8
        for (int dd = 0; dd < 128; dd++) acc += base[dd * LQ_] * w[dd];
        g_s1[idx] = acc;
    }
}

// =====================================================================
// k_S: E = qmask*exp(Cw@Qt^T + s0 + s1); Z1 row partials, Z2 col partials.
//   M=128(c), N=128(q), K=128(d) in 2 chunks. A,B both K-major (trans).
// =====================================================================
#define KS_S0 0
#define KS_S1 512
#define KS_QM 1024
#define KS_CM 1536
#define KS_ZS 2048      // 512 f
#define KS_ZC 4096      // 256 f
#define KS_BUF 8192     // 2 x 64KB
#define KS_DYN 139264

__global__ void __launch_bounds__(256, 1) k_S(const int* __restrict__ Qmask,
                                              const int* __restrict__ Cmask) {
    extern __shared__ char sm[];
    u32 sb = s2u(sm);
    int tid = threadIdx.x, lane = tid & 31, wid = tid >> 5;
    int b = blockIdx.z, cB = blockIdx.y * 128, qB = blockIdx.x * 128, qt = blockIdx.x;
    float* s0f = (float*)(sm + KS_S0);
    float* s1f = (float*)(sm + KS_S1);
    int*   qmi = (int*)(sm + KS_QM);
    float* cmk = (float*)(sm + KS_CM);
    float* zs  = (float*)(sm + KS_ZS);
    float* zc  = (float*)(sm + KS_ZC);
    if (tid < 128) {
        s0f[tid] = g_s0[b * LC_ + cB + tid];
        s1f[tid] = g_s1[b * LQ_ + qB + tid];
        qmi[tid] = Qmask[b * LQ_ + qB + tid];
        cmk[tid] = (float)Cmask[b * LC_ + cB + tid];
    }

    const __nv_bfloat16* CwH = (const __nv_bfloat16*)g_Cwhi;
    const __nv_bfloat16* CwL = (const __nv_bfloat16*)g_Cwlo;
    const __nv_bfloat16* QH  = (const __nv_bfloat16*)g_Qhi;
    const __nv_bfloat16* QL  = (const __nv_bfloat16*)g_Qlo;

    u32 buf0 = sb + KS_BUF, buf1 = sb + KS_BUF + 65536;
    // prefetch chunk 0
    cpyR64(buf0,         CwH + (size_t)(b * D_) * LC_ + cB, CwL + (size_t)(b * D_) * LC_ + cB, LC_, tid);
    cpyR64(buf0 + 32768, QH  + (size_t)(b * D_) * LQ_ + qB, QL  + (size_t)(b * D_) * LQ_ + qB, LQ_, tid);
    CP_COMMIT();

    int wm = wid >> 2, wn = wid & 3;
    int m0w = wm * 64, n0w = wn * 32;
    float acc[4][4][4] = {};
    #pragma unroll
    for (int ci = 0; ci < 2; ci++) {
        if (ci == 0) {
            cpyR64(buf1,         CwH + (size_t)(b * D_ + 64) * LC_ + cB, CwL + (size_t)(b * D_ + 64) * LC_ + cB, LC_, tid);
            cpyR64(buf1 + 32768, QH  + (size_t)(b * D_ + 64) * LQ_ + qB, QL  + (size_t)(b * D_ + 64) * LQ_ + qB, LQ_, tid);
            CP_COMMIT();
            CP_WAIT1();
        } else CP_WAIT0();
        __syncthreads();
        u32 bb = ci ? buf1 : buf0;
        mma_chunk<1, 1>(acc, bb, bb + 32768, m0w, n0w, lane);
        __syncthreads();
    }

    // epilogue
    int r = lane >> 2, cp = (lane & 3) * 2;
    float zrow[8] = {}, zcol[8] = {};
    size_t Ebase = ((size_t)b * LC_ + cB) * LQ_ + qB;
    #pragma unroll
    for (int mi = 0; mi < 4; mi++) {
        int m0 = m0w + mi * 16 + r;
        float s0a = s0f[m0], s0b = s0f[m0 + 8];
        float cma = cmk[m0], cmb = cmk[m0 + 8];
        #pragma unroll
        for (int nj = 0; nj < 4; nj++) {
            int q0 = n0w + nj * 8 + cp;
            float s1a = s1f[q0], s1b = s1f[q0 + 1];
            int qa = qmi[q0], qb = qmi[q0 + 1];
            float e00 = qa ? __expf(acc[mi][nj][0] + s0a + s1a) : 0.f;
            float e01 = qb ? __expf(acc[mi][nj][1] + s0a + s1b) : 0.f;
            float e10 = qa ? __expf(acc[mi][nj][2] + s0b + s1a) : 0.f;
            float e11 = qb ? __expf(acc[mi][nj][3] + s0b + s1b) : 0.f;
            zrow[mi * 2]     += e00 + e01;
            zrow[mi * 2 + 1] += e10 + e11;
            zcol[nj * 2]     += cma * e00 + cmb * e10;
            zcol[nj * 2 + 1] += cma * e01 + cmb * e11;
            u32 h00, l00, h01, l01, h10, l10, h11, l11;
            splt(e00, h00, l00); splt(e01, h01, l01);
            splt(e10, h10, l10); splt(e11, h11, l11);
            size_t i0 = (Ebase + (size_t)m0 * LQ_ + q0) >> 1;
            size_t i1 = (Ebase + (size_t)(m0 + 8) * LQ_ + q0) >> 1;
            g_Ehi[i0] = h00 | (h01 << 16);
            g_Elo[i0] = l00 | (l01 << 16);
            g_Ehi[i1] = h10 | (h11 << 16);
            g_Elo[i1] = l10 | (l11 << 16);
        }
    }
    // Z1 row partials
    #pragma unroll
    for (int h = 0; h < 8; h++) {
        float v = zrow[h];
        v += __shfl_xor_sync(0xffffffffu, v, 1);
        v += __shfl_xor_sync(0xffffffffu, v, 2);
        if ((lane & 3) == 0) {
            int m = m0w + (h >> 1) * 16 + ((h & 1) ? 8 : 0) + r;
            zs[m * 4 + wn] = v;
        }
    }
    // Z2 col partials
    #pragma unroll
    for (int j = 0; j < 8; j++) {
        float v = zcol[j];
        v += __shfl_xor_sync(0xffffffffu, v, 4);
        v += __shfl_xor_sync(0xffffffffu, v, 8);
        v += __shfl_xor_sync(0xffffffffu, v, 16);
        zcol[j] = v;
    }
    if (lane < 4) {
        #pragma unroll
        for (int nj = 0; nj < 4; nj++) {
            zc[wm * 128 + n0w + nj * 8 + lane * 2]     = zcol[nj * 2];
            zc[wm * 128 + n0w + nj * 8 + lane * 2 + 1] = zcol[nj * 2 + 1];
        }
    }
    __syncthreads();
    if (tid < 128) {
        g_Z1p[((size_t)b * LC_ + cB + tid) * 4 + qt] =
            zs[tid * 4] + zs[tid * 4 + 1] + zs[tid * 4 + 2] + zs[tid * 4 + 3];
        g_Z2p[((size_t)b * LQ_ + qB + tid) * 16 + blockIdx.y] = zc[tid] + zc[128 + tid];
    }
}

// =====================================================================
// k_T: T[q][d] = rZ2[q] * sum_c E[c,q]*Cm[d,c].  M=q128, N=d128, K=c2048.
// =====================================================================
#define KT_RZ 0
#define KT_BUF 1024
#define KT_DYN 132096

__global__ void __launch_bounds__(256, 1) k_T() {
    extern __shared__ char sm[];
    u32 sb = s2u(sm);
    int tid = threadIdx.x, lane = tid & 31, wid = tid >> 5;
    int b = blockIdx.y, qB = blockIdx.x * 128;
    float* rzs = (float*)(sm + KT_RZ);
    if (tid < 128) {
        const float* p = &g_Z2p[((size_t)b * LQ_ + qB + tid) * 16];
        float s = 0.f;
        #pragma unroll
        for (int t = 0; t < 16; t++) s += p[t];
        rzs[tid] = 1.f / fmaxf(s, 1e-30f);
    }
    const __nv_bfloat16* EH = (const __nv_bfloat16*)g_Ehi;
    const __nv_bfloat16* EL = (const __nv_bfloat16*)g_Elo;
    const __nv_bfloat16* CH = (const __nv_bfloat16*)g_Cmhi;
    const __nv_bfloat16* CL = (const __nv_bfloat16*)g_Cmlo;
    size_t Eoff = (size_t)(b * LC_) * LQ_ + qB;
    size_t Coff = (size_t)(b * D_) * LC_;
    u32 buf[2] = {sb + KT_BUF, sb + KT_BUF + 65536};

    cpyR64 (buf[0],         EH + Eoff, EL + Eoff, LQ_, tid);
    cpyR128(buf[0] + 32768, CH + Coff, CL + Coff, LC_, tid);
    CP_COMMIT();

    int wm = wid >> 2, wn = wid & 3;
    int m0w = wm * 64, n0w = wn * 32;
    float acc[4][4][4] = {};
    for (int ci = 0; ci < 32; ci++) {
        if (ci + 1 < 32) {
            int c0 = (ci + 1) * 64;
            u32 bb = buf[(ci + 1) & 1];
            cpyR64 (bb,         EH + Eoff + (size_t)c0 * LQ_, EL + Eoff + (size_t)c0 * LQ_, LQ_, tid);
            cpyR128(bb + 32768, CH + Coff + c0,               CL + Coff + c0,               LC_, tid);
            CP_COMMIT();
            CP_WAIT1();
        } else CP_WAIT0();
        __syncthreads();
        u32 bb = buf[ci & 1];
        mma_chunk<1, 0>(acc, bb, bb + 32768, m0w, n0w, lane);
        __syncthreads();
    }

    int r = lane >> 2, cp = (lane & 3) * 2;
    #pragma unroll
    for (int mi = 0; mi < 4; mi++) {
        int q0 = m0w + mi * 16 + r;
        float rza = rzs[q0], rzb = rzs[q0 + 8];
        #pragma unroll
        for (int nj = 0; nj < 4; nj++) {
            int d0 = n0w + nj * 8 + cp;
            u32 h0, l0, h1, l1;
            size_t i0 = ((size_t)(b * LQ_ + qB + q0) * D_ + d0) >> 1;
            size_t i1 = ((size_t)(b * LQ_ + qB + q0 + 8) * D_ + d0) >> 1;
            splt(acc[mi][nj][0] * rza, h0, l0); splt(acc[mi][nj][1] * rza, h1, l1);
            g_Thi[i0] = h0 | (h1 << 16); g_Tlo[i0] = l0 | (l1 << 16);
            splt(acc[mi][nj][2] * rzb, h0, l0); splt(acc[mi][nj][3] * rzb, h1, l1);
            g_Thi[i1] = h0 | (h1 << 16); g_Tlo[i1] = l0 | (l1 << 16);
        }
    }
}

// =====================================================================
// k_AB: mode0: D=E@Qt -> sections 0,1,2 ; mode1: D=E@T -> section 3.
//   M=c128, N=d128, K=q512 in 8 chunks. rZ1 applied in epilogue.
// =====================================================================
#define KA_RZ 0
#define KA_BUF 1024
#define KA_DYN 132096

__global__ void __launch_bounds__(256, 1) k_AB(const float* __restrict__ C,
                                               float* __restrict__ out) {
    extern __shared__ char sm[];
    u32 sb = s2u(sm);
    int tid = threadIdx.x, lane = tid & 31, wid = tid >> 5;
    int b = blockIdx.y, cB = blockIdx.x * 128, mode = blockIdx.z;
    float* rzs = (float*)(sm + KA_RZ);
    if (tid < 128) {
        const float* p = &g_Z1p[((size_t)b * LC_ + cB + tid) * 4];
        rzs[tid] = 1.f / (p[0] + p[1] + p[2] + p[3]);
    }
    const __nv_bfloat16* EH = (const __nv_bfloat16*)g_Ehi;
    const __nv_bfloat16* EL = (const __nv_bfloat16*)g_Elo;
    const __nv_bfloat16* QH = (const __nv_bfloat16*)g_Qhi;
    const __nv_bfloat16* QL = (const __nv_bfloat16*)g_Qlo;
    const __nv_bfloat16* TH = (const __nv_bfloat16*)g_Thi;
    const __nv_bfloat16* TL = (const __nv_bfloat16*)g_Tlo;
    size_t Eoff = ((size_t)b * LC_ + cB) * LQ_;
    size_t Qoff = (size_t)(b * D_) * LQ_;
    size_t Toff = (size_t)(b * LQ_) * D_;
    u32 buf[2] = {sb + KA_BUF, sb + KA_BUF + 65536};

    cpyR128(buf[0], EH + Eoff, EL + Eoff, LQ_, tid);
    if (mode == 0) cpyR128(buf[0] + 32768, QH + Qoff, QL + Qoff, LQ_, tid);
    else           cpyR64 (buf[0] + 32768, TH + Toff, TL + Toff, D_, tid);
    CP_COMMIT();

    int wm = wid >> 2, wn = wid & 3;
    int m0w = wm * 64, n0w = wn * 32;
    float acc[4][4][4] = {};
    for (int ci = 0; ci < 8; ci++) {
        if (ci + 1 < 8) {
            int q0 = (ci + 1) * 64;
            u32 bb = buf[(ci + 1) & 1];
            cpyR128(bb, EH + Eoff + q0, EL + Eoff + q0, LQ_, tid);
            if (mode == 0) cpyR128(bb + 32768, QH + Qoff + q0, QL + Qoff + q0, LQ_, tid);
            else           cpyR64 (bb + 32768, TH + Toff + (size_t)q0 * D_, TL + Toff + (size_t)q0 * D_, D_, tid);
            CP_COMMIT();
            CP_WAIT1();
        } else CP_WAIT0();
        __syncthreads();
        u32 bb = buf[ci & 1];
        if (mode == 0) mma_chunk<0, 0>(acc, bb, bb + 32768, m0w, n0w, lane);
        else           mma_chunk<0, 1>(acc, bb, bb + 32768, m0w, n0w, lane);
        __syncthreads();
    }

    // stage [d][c] (pitch 132) with rZ1, then assemble output
    float* stg = (float*)(sm + KA_BUF);
    int r = lane >> 2, cp = (lane & 3) * 2;
    #pragma unroll
    for (int mi = 0; mi < 4; mi++) {
        int m0 = m0w + mi * 16 + r;
        float rza = rzs[m0], rzb = rzs[m0 + 8];
        #pragma unroll
        for (int nj = 0; nj < 4; nj++) {
            int n0 = n0w + nj * 8 + cp;
            stg[n0 * 132 + m0]           = acc[mi][nj][0] * rza;
            stg[(n0 + 1) * 132 + m0]     = acc[mi][nj][1] * rza;
            stg[n0 * 132 + m0 + 8]       = acc[mi][nj][2] * rzb;
            stg[(n0 + 1) * 132 + m0 + 8] = acc[mi][nj][3] * rzb;
        }
    }
    __syncthreads();
    const float* Cb = C + (size_t)b * D_ * LC_ + cB;
    float* ob = out + (size_t)b * 4 * D_ * LC_ + cB;
    if (mode == 0) {
        for (int idx = tid; idx < 128 * 128; idx += 256) {
            int dd = idx >> 7, c = idx & 127;
            float a = stg[dd * 132 + c];
            float cv = Cb[(size_t)dd * LC_ + c];
            ob[(size_t)dd * LC_ + c]         = cv;
            ob[(size_t)(128 + dd) * LC_ + c] = a;
            ob[(size_t)(256 + dd) * LC_ + c] = cv * a;
        }
    } else {
        for (int idx = tid; idx < 128 * 128; idx += 256) {
            int dd = idx >> 7, c = idx & 127;
            float bm = stg[dd * 132 + c];
            float cv = Cb[(size_t)dd * LC_ + c];
            ob[(size_t)(384 + dd) * LC_ + c] = cv * bm;
        }
    }
}

// =====================================================================
extern "C" void kernel_launch(void* const* d_in, const int* in_sizes, int n_in,
                              void* d_out, int out_size) {
    const float* C     = (const float*)d_in[0];
    const float* Q     = (const float*)d_in[1];
    const int*   Cmask = (const int*)  d_in[2];
    const int*   Qmask = (const int*)  d_in[3];
    const float* w_c   = (const float*)d_in[4];
    const float* w_q   = (const float*)d_in[5];
    const float* w_mul = (const float*)d_in[6];
    const float* bias  = (const float*)d_in[7];
    float* out = (float*)d_out;

    cudaFuncSetAttribute(k_S,  cudaFuncAttributeMaxDynamicSharedMemorySize, KS_DYN);
    cudaFuncSetAttribute(k_T,  cudaFuncAttributeMaxDynamicSharedMemorySize, KT_DYN);
    cudaFuncSetAttribute(k_AB, cudaFuncAttributeMaxDynamicSharedMemorySize, KA_DYN);

    k_cvtC<<<(B_ * D_ * LC_ / 4) / 256, 256>>>(C, Cmask, w_mul);
    k_cvtQ<<<(B_ * D_ * LQ_ / 4) / 256, 256>>>(Q);
    k_vec<<<320, 256>>>(C, Q, w_c, w_q, bias);
    k_S<<<dim3(4, 16, 32), 256, KS_DYN>>>(Qmask, Cmask);
    k_T<<<dim3(4, 32), 256, KT_DYN>>>();
    k_AB<<<dim3(16, 32, 2), 256, KA_DYN>>>(C, out);
}